// round 7
// baseline (speedup 1.0000x reference)
#include <cuda_runtime.h>

#define DIMV 64
#define MAX_NODES  100000
#define CAP        64          // per-node incidence capacity (Poisson(20) tail ~0)
#define OVER_CAP   2000000     // >= 2*E : overflow can never drop

// Zero at module load; every kernel_launch call restores its state
// (node_kernel zeroes g_cnt after reading; finalize resets energy/over_cnt).
__device__ int   g_cnt[MAX_NODES];
__device__ int   g_slots[MAX_NODES * CAP];
__device__ int2  g_over[OVER_CAP];
__device__ int   g_over_cnt;
__device__ float g_energy;

__device__ __forceinline__ void red_add_f32(float* addr, float a) {
    asm volatile("red.global.add.f32 [%0], %1;"
                 :: "l"(addr), "f"(a) : "memory");
}

// ---------------------------------------------------------------------------
// Phase 1: symmetric binning — each edge (u,v) inserted under u AND under v.
// ---------------------------------------------------------------------------
__global__ __launch_bounds__(512)
void build_kernel(const int* __restrict__ u_idx,
                  const int* __restrict__ v_idx,
                  int E) {
    int e = blockIdx.x * blockDim.x + threadIdx.x;
    if (e >= E) return;
    int u = u_idx[e];
    int v = v_idx[e];
    int pu = atomicAdd(&g_cnt[u], 1);
    int pv = atomicAdd(&g_cnt[v], 1);
    if (pu < CAP) g_slots[u * CAP + pu] = v;
    else { int o = atomicAdd(&g_over_cnt, 1); g_over[o] = make_int2(u, v); }
    if (pv < CAP) g_slots[v * CAP + pv] = u;
    else { int o = atomicAdd(&g_over_cnt, 1); g_over[o] = make_int2(v, u); }
}

// ---------------------------------------------------------------------------
// Phase 2: node-centric, fully register-accumulated. 8 lanes per node.
// Writes the node's grad row straight to d_out (plain stores, no atomics).
// In-loop shuffles use the 8-lane group mask (trip count differs per group).
// ---------------------------------------------------------------------------
__global__ __launch_bounds__(512)
void node_kernel(const float* __restrict__ x, float* __restrict__ out, int N) {
    int gid  = blockIdx.x * blockDim.x + threadIdx.x;
    int u    = gid >> 3;
    int sub  = gid & 7;
    int lane = threadIdx.x & 31;
    unsigned gmask = 0xFFu << (lane & ~7);

    float e_acc = 0.0f;

    if (u < N) {
        const float4* pu = reinterpret_cast<const float4*>(x + (size_t)u * DIMV) + 2 * sub;
        float4 a0 = pu[0], a1 = pu[1];
        float sgn = (sub == 0) ? -1.0f : 1.0f;

        int cnt = g_cnt[u];
        if (sub == 0) g_cnt[u] = 0;                // restore-to-zero for next call
        if (cnt > CAP) cnt = CAP;
        const int* slots = g_slots + u * CAP;

        float4 ua0 = make_float4(0.f, 0.f, 0.f, 0.f);
        float4 ua1 = make_float4(0.f, 0.f, 0.f, 0.f);

        // software pipeline: keep next partner's row in flight
        float4 b0, b1;
        if (cnt > 0) {
            int v0 = slots[0];
            const float4* pv = reinterpret_cast<const float4*>(x + (size_t)v0 * DIMV) + 2 * sub;
            b0 = pv[0]; b1 = pv[1];
        }
        for (int i = 0; i < cnt; i++) {
            float4 c0 = b0, c1 = b1;
            if (i + 1 < cnt) {
                int vn = slots[i + 1];
                const float4* pv = reinterpret_cast<const float4*>(x + (size_t)vn * DIMV) + 2 * sub;
                b0 = pv[0]; b1 = pv[1];
            }

            float partial = sgn * (a0.x * c0.x) + a0.y * c0.y + a0.z * c0.z + a0.w * c0.w
                          + a1.x * c1.x + a1.y * c1.y + a1.z * c1.z + a1.w * c1.w;
            partial += __shfl_xor_sync(gmask, partial, 1);
            partial += __shfl_xor_sync(gmask, partial, 2);
            partial += __shfl_xor_sync(gmask, partial, 4);

            float inner = fminf(partial, -1.0f - 1e-7f);
            float s     = sqrtf(inner * inner - 1.0f);      // same fp32 form as reference
            float dist  = logf(-inner + s);                 // acosh(-inner)
            float delta = fmaxf(0.1f - dist, 0.0f);         // 0 when inactive -> factor 0
            float factor = -__fdividef(10.0f * delta, s + 1e-9f);

            if (sub == 0) e_acc += 2.5f * delta * delta;    // 0.5 * (5*delta^2) per directed copy

            ua0.x += sgn * factor * c0.x;
            ua0.y += factor * c0.y;  ua0.z += factor * c0.z;  ua0.w += factor * c0.w;
            ua1.x += factor * c1.x;  ua1.y += factor * c1.y;
            ua1.z += factor * c1.z;  ua1.w += factor * c1.w;
        }

        // write this node's grad slice directly (out+1 is only 4B-aligned)
        float* og = out + 1 + (size_t)u * DIMV + 8 * sub;
        og[0] = ua0.x; og[1] = ua0.y; og[2] = ua0.z; og[3] = ua0.w;
        og[4] = ua1.x; og[5] = ua1.y; og[6] = ua1.z; og[7] = ua1.w;
    }

    // block energy reduction (all lanes reconverged) -> one RED per block
    e_acc += __shfl_xor_sync(0xffffffffu, e_acc, 16);
    e_acc += __shfl_xor_sync(0xffffffffu, e_acc, 8);
    e_acc += __shfl_xor_sync(0xffffffffu, e_acc, 4);
    e_acc += __shfl_xor_sync(0xffffffffu, e_acc, 2);
    e_acc += __shfl_xor_sync(0xffffffffu, e_acc, 1);

    __shared__ float smem[16];
    int warp = threadIdx.x >> 5;
    if (lane == 0) smem[warp] = e_acc;
    __syncthreads();
    if (warp == 0) {
        float ss = (lane < 16) ? smem[lane] : 0.0f;
        ss += __shfl_xor_sync(0xffffffffu, ss, 8);
        ss += __shfl_xor_sync(0xffffffffu, ss, 4);
        ss += __shfl_xor_sync(0xffffffffu, ss, 2);
        ss += __shfl_xor_sync(0xffffffffu, ss, 1);
        if (lane == 0 && ss != 0.0f) red_add_f32(&g_energy, ss);
    }
}

// ---------------------------------------------------------------------------
// Phase 3: single block — process (normally empty) overflow list with atomics
// on top of the plain-stored grad, then emit energy and reset scratch.
// ---------------------------------------------------------------------------
__global__ void finalize_kernel(const float* __restrict__ x, float* __restrict__ out) {
    int oc = g_over_cnt;
    float e_local = 0.0f;
    for (int i = threadIdx.x; i < oc; i += blockDim.x) {
        int w = g_over[i].x, p = g_over[i].y;
        const float* xw = x + (size_t)w * DIMV;
        const float* xp = x + (size_t)p * DIMV;
        float dot = -xw[0] * xp[0];
        for (int k = 1; k < DIMV; k++) dot += xw[k] * xp[k];
        float inner = fminf(dot, -1.0f - 1e-7f);
        float s     = sqrtf(inner * inner - 1.0f);
        float dist  = logf(-inner + s);
        if (dist < 0.1f) {
            float delta  = 0.1f - dist;
            float factor = -(10.0f * delta) / (s + 1e-9f);
            e_local += 2.5f * delta * delta;
            float* gw = out + 1 + (size_t)w * DIMV;
            atomicAdd(gw + 0, -factor * xp[0]);
            for (int k = 1; k < DIMV; k++) atomicAdd(gw + k, factor * xp[k]);
        }
    }
    if (e_local != 0.0f) atomicAdd(&g_energy, e_local);
    __syncthreads();
    if (threadIdx.x == 0) {
        out[0] = g_energy;
        g_energy = 0.0f;
        g_over_cnt = 0;
    }
}

extern "C" void kernel_launch(void* const* d_in, const int* in_sizes, int n_in,
                              void* d_out, int out_size) {
    const float* x     = (const float*)d_in[0];
    const int*   u_idx = (const int*)d_in[1];
    const int*   v_idx = (const int*)d_in[2];
    float*       out   = (float*)d_out;

    int E = in_sizes[1];           // edges
    int N = in_sizes[0] / DIMV;    // nodes

    build_kernel<<<(E + 511) / 512, 512>>>(u_idx, v_idx, E);

    long long lanes = (long long)N * 8;
    node_kernel<<<(int)((lanes + 511) / 512), 512>>>(x, out, N);

    finalize_kernel<<<1, 256>>>(x, out);
}

// round 9
// speedup vs baseline: 1.0177x; 1.0177x over previous
#include <cuda_runtime.h>

#define DIMV 64
#define GRAD_ELEMS 6400000   // N * DIM
#define GRAD_V4    1600000   // GRAD_ELEMS / 4
#define MAX_NODES  100000
#define CAP        64        // per-node slot capacity (Poisson(10) tail ~0)
#define OVER_CAP   1000000   // >= E: overflow can never drop

// Zero at module load. Per-call restore protocol (stream-ordered):
//   build(k):  zeroes g_grad (copy(k-1) already read it), bins edges
//   node(k):   accumulates g_grad, zeroes g_cnt, tail threads drain g_over
//   copy(k):   reads g_grad -> out, resets g_energy/g_over_cnt
__device__ float g_grad[GRAD_ELEMS];
__device__ float g_energy;
__device__ int   g_cnt[MAX_NODES];
__device__ int   g_slots[MAX_NODES * CAP];
__device__ int2  g_over[OVER_CAP];
__device__ int   g_over_cnt;

__device__ __forceinline__ void red_add_v4(float* addr, float a, float b, float c, float d) {
    asm volatile("red.global.add.v4.f32 [%0], {%1, %2, %3, %4};"
                 :: "l"(addr), "f"(a), "f"(b), "f"(c), "f"(d)
                 : "memory");
}
__device__ __forceinline__ void red_add_f32(float* addr, float a) {
    asm volatile("red.global.add.f32 [%0], %1;"
                 :: "l"(addr), "f"(a) : "memory");
}

// ---------------------------------------------------------------------------
// Phase 1: bin edges by u; also zero g_grad (overlaps the latency-bound
// atomics; removes the zero-writeback from the copy kernel).
// ---------------------------------------------------------------------------
__global__ __launch_bounds__(512)
void build_kernel(const int* __restrict__ u_idx,
                  const int* __restrict__ v_idx,
                  int E) {
    int e = blockIdx.x * blockDim.x + threadIdx.x;
    int total = gridDim.x * blockDim.x;

    // zero g_grad (grid-stride)
    float4* g = reinterpret_cast<float4*>(g_grad);
    float4 z = make_float4(0.f, 0.f, 0.f, 0.f);
    for (int j = e; j < GRAD_V4; j += total) g[j] = z;

    if (e >= E) return;
    int u = u_idx[e];
    int v = v_idx[e];
    int pos = atomicAdd(&g_cnt[u], 1);
    if (pos < CAP) {
        g_slots[u * CAP + pos] = v;
    } else {
        int o = atomicAdd(&g_over_cnt, 1);
        g_over[o] = make_int2(u, v);
    }
}

// ---------------------------------------------------------------------------
// Phase 2: node-centric. 8 lanes per node u; xu loaded once; u-grad in
// registers; v-grad scattered with red.v4. Depth-2 pipeline on partner rows.
// In-loop shuffles use the 8-lane GROUP mask (cnt differs per group).
// Tail threads (u >= N) drain the overflow list with scalar atomics.
// ---------------------------------------------------------------------------
__global__ __launch_bounds__(512)
void node_kernel(const float* __restrict__ x, int N) {
    int gid  = blockIdx.x * blockDim.x + threadIdx.x;
    int u    = gid >> 3;
    int sub  = gid & 7;
    int lane = threadIdx.x & 31;
    unsigned gmask = 0xFFu << (lane & ~7);

    float e_acc = 0.0f;

    if (u < N) {
        const float4* pu = reinterpret_cast<const float4*>(x + (size_t)u * DIMV) + 2 * sub;
        float4 a0 = pu[0], a1 = pu[1];
        float sgn = (sub == 0) ? -1.0f : 1.0f;

        int cnt = g_cnt[u];
        if (sub == 0) g_cnt[u] = 0;          // restore for next call
        if (cnt > CAP) cnt = CAP;
        const int* slots = g_slots + u * CAP;

        float4 ua0 = make_float4(0.f, 0.f, 0.f, 0.f);
        float4 ua1 = make_float4(0.f, 0.f, 0.f, 0.f);
        bool any_active = false;

        // depth-2 pipeline: two partner rows in flight
        float4 p0[2], p1[2];
        if (cnt > 0) {
            const float4* pv = reinterpret_cast<const float4*>(x + (size_t)slots[0] * DIMV) + 2 * sub;
            p0[0] = pv[0]; p1[0] = pv[1];
        }
        if (cnt > 1) {
            const float4* pv = reinterpret_cast<const float4*>(x + (size_t)slots[1] * DIMV) + 2 * sub;
            p0[1] = pv[0]; p1[1] = pv[1];
        }

        for (int i = 0; i < cnt; i++) {
            float4 c0 = p0[i & 1], c1 = p1[i & 1];
            if (i + 2 < cnt) {
                const float4* pv = reinterpret_cast<const float4*>(x + (size_t)slots[i + 2] * DIMV) + 2 * sub;
                p0[i & 1] = pv[0]; p1[i & 1] = pv[1];
            }

            float partial = sgn * (a0.x * c0.x) + a0.y * c0.y + a0.z * c0.z + a0.w * c0.w
                          + a1.x * c1.x + a1.y * c1.y + a1.z * c1.z + a1.w * c1.w;
            partial += __shfl_xor_sync(gmask, partial, 1);
            partial += __shfl_xor_sync(gmask, partial, 2);
            partial += __shfl_xor_sync(gmask, partial, 4);

            float inner = fminf(partial, -1.0f - 1e-7f);
            float s     = sqrtf(inner * inner - 1.0f);      // same fp32 form as reference
            float dist  = logf(-inner + s);                 // acosh(-inner)
            float delta = fmaxf(0.1f - dist, 0.0f);
            float factor = -__fdividef(10.0f * delta, s + 1e-9f);

            if (sub == 0) e_acc += 5.0f * delta * delta;    // 0 when inactive

            // u-side: register accumulate (factor==0 harmless)
            ua0.x += sgn * factor * c0.x;
            ua0.y += factor * c0.y;  ua0.z += factor * c0.z;  ua0.w += factor * c0.w;
            ua1.x += factor * c1.x;  ua1.y += factor * c1.y;
            ua1.z += factor * c1.z;  ua1.w += factor * c1.w;

            // v-side: scatter only when active (saves atomic bytes)
            if (delta > 0.0f) {
                any_active = true;
                float* dv = g_grad + (size_t)slots[i] * DIMV + 8 * sub;
                red_add_v4(dv,     sgn * factor * a0.x, factor * a0.y, factor * a0.z, factor * a0.w);
                red_add_v4(dv + 4, factor * a1.x,       factor * a1.y, factor * a1.z, factor * a1.w);
            }
        }

        if (any_active) {
            float* du = g_grad + (size_t)u * DIMV + 8 * sub;
            red_add_v4(du,     ua0.x, ua0.y, ua0.z, ua0.w);
            red_add_v4(du + 4, ua1.x, ua1.y, ua1.z, ua1.w);
        }
    } else {
        // tail threads: drain overflow list (normally empty)
        int base = N * 8;
        int nthreads = gridDim.x * blockDim.x - base;
        int oc = g_over_cnt;
        for (int i = gid - base; i < oc; i += nthreads) {
            int w = g_over[i].x, p = g_over[i].y;
            const float* xw = x + (size_t)w * DIMV;
            const float* xp = x + (size_t)p * DIMV;
            float dot = -xw[0] * xp[0];
            for (int k = 1; k < DIMV; k++) dot += xw[k] * xp[k];
            float inner = fminf(dot, -1.0f - 1e-7f);
            float s     = sqrtf(inner * inner - 1.0f);
            float dist  = logf(-inner + s);
            if (dist < 0.1f) {
                float delta  = 0.1f - dist;
                float factor = -(10.0f * delta) / (s + 1e-9f);
                e_acc += 5.0f * delta * delta;
                float* gw = g_grad + (size_t)w * DIMV;
                float* gp = g_grad + (size_t)p * DIMV;
                atomicAdd(gw + 0, -factor * xp[0]);
                atomicAdd(gp + 0, -factor * xw[0]);
                for (int k = 1; k < DIMV; k++) {
                    atomicAdd(gw + k, factor * xp[k]);
                    atomicAdd(gp + k, factor * xw[k]);
                }
            }
        }
    }

    // block energy reduction (all lanes reconverged) -> one RED per block
    e_acc += __shfl_xor_sync(0xffffffffu, e_acc, 16);
    e_acc += __shfl_xor_sync(0xffffffffu, e_acc, 8);
    e_acc += __shfl_xor_sync(0xffffffffu, e_acc, 4);
    e_acc += __shfl_xor_sync(0xffffffffu, e_acc, 2);
    e_acc += __shfl_xor_sync(0xffffffffu, e_acc, 1);

    __shared__ float smem[16];
    int warp = threadIdx.x >> 5;
    if (lane == 0) smem[warp] = e_acc;
    __syncthreads();
    if (warp == 0) {
        float ss = (lane < 16) ? smem[lane] : 0.0f;
        ss += __shfl_xor_sync(0xffffffffu, ss, 8);
        ss += __shfl_xor_sync(0xffffffffu, ss, 4);
        ss += __shfl_xor_sync(0xffffffffu, ss, 2);
        ss += __shfl_xor_sync(0xffffffffu, ss, 1);
        if (lane == 0 && ss != 0.0f) red_add_f32(&g_energy, ss);
    }
}

// ---------------------------------------------------------------------------
// Phase 3: copy grad -> d_out (unaligned by 1 float), emit energy, reset
// scalars. No g_grad zeroing here — next call's build does it.
// ---------------------------------------------------------------------------
__global__ __launch_bounds__(512)
void copy_kernel(float* __restrict__ out, int n_grad4) {
    int j = blockIdx.x * blockDim.x + threadIdx.x;
    if (j < n_grad4) {
        const float4* g = reinterpret_cast<const float4*>(g_grad);
        float4 val = g[j];
        float* out_grad = out + 1;
        out_grad[4 * j + 0] = val.x;
        out_grad[4 * j + 1] = val.y;
        out_grad[4 * j + 2] = val.z;
        out_grad[4 * j + 3] = val.w;
    }
    if (j == 0) {
        out[0] = g_energy;
        g_energy = 0.0f;
        g_over_cnt = 0;
    }
}

extern "C" void kernel_launch(void* const* d_in, const int* in_sizes, int n_in,
                              void* d_out, int out_size) {
    const float* x     = (const float*)d_in[0];
    const int*   u_idx = (const int*)d_in[1];
    const int*   v_idx = (const int*)d_in[2];
    float*       out   = (float*)d_out;

    int E  = in_sizes[1];          // edges
    int n4 = in_sizes[0] / 4;      // grad float4 count
    int N  = in_sizes[0] / DIMV;   // nodes

    build_kernel<<<(E + 511) / 512, 512>>>(u_idx, v_idx, E);

    long long lanes = (long long)N * 8;
    int nblocks = (int)((lanes + 511) / 512) + 1;   // +1 block: overflow drain
    node_kernel<<<nblocks, 512>>>(x, N);

    copy_kernel<<<(n4 + 511) / 512, 512>>>(out, n4);
}

// round 14
// speedup vs baseline: 1.1704x; 1.1501x over previous
#include <cuda_runtime.h>

#define DIMV 64
#define GRAD_ELEMS 6400000   // N * DIM
#define GRAD_V4    1600000   // GRAD_ELEMS / 4
#define MAX_NODES  100000
#define CAP        64        // per-node slot capacity (Poisson(10) tail ~0)
#define OVER_CAP   1000000   // >= E: overflow can never drop

// Zero at module load. Per-call restore protocol (stream-ordered):
//   build(k):  zeroes g_grad (copy(k-1) already read it), bins edges
//   node(k):   accumulates g_grad, zeroes g_cnt, tail block drains g_over
//   copy(k):   reads g_grad -> out, resets g_energy/g_over_cnt
__device__ float g_grad[GRAD_ELEMS];
__device__ float g_energy;
__device__ int   g_cnt[MAX_NODES];
__device__ int   g_slots[MAX_NODES * CAP];
__device__ int2  g_over[OVER_CAP];
__device__ int   g_over_cnt;

__device__ __forceinline__ void red_add_v4(float* addr, float a, float b, float c, float d) {
    asm volatile("red.global.add.v4.f32 [%0], {%1, %2, %3, %4};"
                 :: "l"(addr), "f"(a), "f"(b), "f"(c), "f"(d)
                 : "memory");
}
__device__ __forceinline__ void red_add_f32(float* addr, float a) {
    asm volatile("red.global.add.f32 [%0], %1;"
                 :: "l"(addr), "f"(a) : "memory");
}

// ---------------------------------------------------------------------------
// Phase 1: bin edges by u; also zero g_grad (overlaps the latency-bound
// binning atomics).
// ---------------------------------------------------------------------------
__global__ __launch_bounds__(512)
void build_kernel(const int* __restrict__ u_idx,
                  const int* __restrict__ v_idx,
                  int E) {
    int e = blockIdx.x * blockDim.x + threadIdx.x;
    int total = gridDim.x * blockDim.x;

    float4* g = reinterpret_cast<float4*>(g_grad);
    float4 z = make_float4(0.f, 0.f, 0.f, 0.f);
    for (int j = e; j < GRAD_V4; j += total) g[j] = z;

    if (e >= E) return;
    int u = u_idx[e];
    int v = v_idx[e];
    int pos = atomicAdd(&g_cnt[u], 1);
    if (pos < CAP) {
        g_slots[u * CAP + pos] = v;
    } else {
        int o = atomicAdd(&g_over_cnt, 1);
        g_over[o] = make_int2(u, v);
    }
}

// ---------------------------------------------------------------------------
// Phase 2: node-centric. 8 lanes per node u; xu loaded once; u-grad in
// registers; v-grad scattered with red.v4 only when active. Depth-1 prefetch
// with NAMED variables only (no local arrays -> no LDL/STL spills).
// In-loop shuffles use the 8-lane GROUP mask (cnt differs per group).
// Tail threads (u >= N) drain the overflow list.
// ---------------------------------------------------------------------------
__global__ __launch_bounds__(512)
void node_kernel(const float* __restrict__ x, int N) {
    int gid  = blockIdx.x * blockDim.x + threadIdx.x;
    int u    = gid >> 3;
    int sub  = gid & 7;
    int lane = threadIdx.x & 31;
    unsigned gmask = 0xFFu << (lane & ~7);

    float e_acc = 0.0f;

    if (u < N) {
        const float4* pu = reinterpret_cast<const float4*>(x + (size_t)u * DIMV) + 2 * sub;
        float4 a0 = pu[0], a1 = pu[1];
        float sgn = (sub == 0) ? -1.0f : 1.0f;

        int cnt = g_cnt[u];
        if (sub == 0) g_cnt[u] = 0;          // restore for next call
        if (cnt > CAP) cnt = CAP;
        const int* slots = g_slots + u * CAP;

        float4 ua0 = make_float4(0.f, 0.f, 0.f, 0.f);
        float4 ua1 = make_float4(0.f, 0.f, 0.f, 0.f);
        bool any_active = false;

        // depth-1 prefetch, named registers only
        float4 nb0, nb1;
        if (cnt > 0) {
            const float4* pv = reinterpret_cast<const float4*>(x + (size_t)slots[0] * DIMV) + 2 * sub;
            nb0 = pv[0]; nb1 = pv[1];
        }

        for (int i = 0; i < cnt; i++) {
            float4 c0 = nb0, c1 = nb1;
            if (i + 1 < cnt) {
                const float4* pv = reinterpret_cast<const float4*>(x + (size_t)slots[i + 1] * DIMV) + 2 * sub;
                nb0 = pv[0]; nb1 = pv[1];
            }

            float partial = sgn * (a0.x * c0.x) + a0.y * c0.y + a0.z * c0.z + a0.w * c0.w
                          + a1.x * c1.x + a1.y * c1.y + a1.z * c1.z + a1.w * c1.w;
            partial += __shfl_xor_sync(gmask, partial, 1);
            partial += __shfl_xor_sync(gmask, partial, 2);
            partial += __shfl_xor_sync(gmask, partial, 4);

            float inner = fminf(partial, -1.0f - 1e-7f);
            float s     = sqrtf(inner * inner - 1.0f);      // same fp32 form as reference
            float dist  = logf(-inner + s);                 // acosh(-inner)

            if (dist < 0.1f) {
                any_active = true;
                float delta = 0.1f - dist;
                if (sub == 0) e_acc += 5.0f * delta * delta;

                float factor = -__fdividef(10.0f * delta, s + 1e-9f);

                ua0.x += sgn * factor * c0.x;
                ua0.y += factor * c0.y;  ua0.z += factor * c0.z;  ua0.w += factor * c0.w;
                ua1.x += factor * c1.x;  ua1.y += factor * c1.y;
                ua1.z += factor * c1.z;  ua1.w += factor * c1.w;

                float* dv = g_grad + (size_t)slots[i] * DIMV + 8 * sub;
                red_add_v4(dv,     sgn * factor * a0.x, factor * a0.y, factor * a0.z, factor * a0.w);
                red_add_v4(dv + 4, factor * a1.x,       factor * a1.y, factor * a1.z, factor * a1.w);
            }
        }

        if (any_active) {
            float* du = g_grad + (size_t)u * DIMV + 8 * sub;
            red_add_v4(du,     ua0.x, ua0.y, ua0.z, ua0.w);
            red_add_v4(du + 4, ua1.x, ua1.y, ua1.z, ua1.w);
        }
    } else {
        // tail threads: drain overflow list (normally empty)
        int base = N * 8;
        int nthreads = gridDim.x * blockDim.x - base;
        int oc = g_over_cnt;
        for (int i = gid - base; i < oc; i += nthreads) {
            int w = g_over[i].x, p = g_over[i].y;
            const float* xw = x + (size_t)w * DIMV;
            const float* xp = x + (size_t)p * DIMV;
            float dot = -xw[0] * xp[0];
            for (int k = 1; k < DIMV; k++) dot += xw[k] * xp[k];
            float inner = fminf(dot, -1.0f - 1e-7f);
            float s     = sqrtf(inner * inner - 1.0f);
            float dist  = logf(-inner + s);
            if (dist < 0.1f) {
                float delta  = 0.1f - dist;
                float factor = -(10.0f * delta) / (s + 1e-9f);
                e_acc += 5.0f * delta * delta;
                float* gw = g_grad + (size_t)w * DIMV;
                float* gp = g_grad + (size_t)p * DIMV;
                atomicAdd(gw + 0, -factor * xp[0]);
                atomicAdd(gp + 0, -factor * xw[0]);
                for (int k = 1; k < DIMV; k++) {
                    atomicAdd(gw + k, factor * xp[k]);
                    atomicAdd(gp + k, factor * xw[k]);
                }
            }
        }
    }

    // block energy reduction (all lanes reconverged) -> one RED per block
    e_acc += __shfl_xor_sync(0xffffffffu, e_acc, 16);
    e_acc += __shfl_xor_sync(0xffffffffu, e_acc, 8);
    e_acc += __shfl_xor_sync(0xffffffffu, e_acc, 4);
    e_acc += __shfl_xor_sync(0xffffffffu, e_acc, 2);
    e_acc += __shfl_xor_sync(0xffffffffu, e_acc, 1);

    __shared__ float smem[16];
    int warp = threadIdx.x >> 5;
    if (lane == 0) smem[warp] = e_acc;
    __syncthreads();
    if (warp == 0) {
        float ss = (lane < 16) ? smem[lane] : 0.0f;
        ss += __shfl_xor_sync(0xffffffffu, ss, 8);
        ss += __shfl_xor_sync(0xffffffffu, ss, 4);
        ss += __shfl_xor_sync(0xffffffffu, ss, 2);
        ss += __shfl_xor_sync(0xffffffffu, ss, 1);
        if (lane == 0 && ss != 0.0f) red_add_f32(&g_energy, ss);
    }
}

// ---------------------------------------------------------------------------
// Phase 3: copy grad -> d_out (unaligned by 1 float), emit energy, reset
// scalars. No g_grad zeroing here — next call's build does it.
// ---------------------------------------------------------------------------
__global__ __launch_bounds__(512)
void copy_kernel(float* __restrict__ out, int n_grad4) {
    int j = blockIdx.x * blockDim.x + threadIdx.x;
    if (j < n_grad4) {
        const float4* g = reinterpret_cast<const float4*>(g_grad);
        float4 val = g[j];
        float* out_grad = out + 1;
        out_grad[4 * j + 0] = val.x;
        out_grad[4 * j + 1] = val.y;
        out_grad[4 * j + 2] = val.z;
        out_grad[4 * j + 3] = val.w;
    }
    if (j == 0) {
        out[0] = g_energy;
        g_energy = 0.0f;
        g_over_cnt = 0;
    }
}

extern "C" void kernel_launch(void* const* d_in, const int* in_sizes, int n_in,
                              void* d_out, int out_size) {
    const float* x     = (const float*)d_in[0];
    const int*   u_idx = (const int*)d_in[1];
    const int*   v_idx = (const int*)d_in[2];
    float*       out   = (float*)d_out;

    int E  = in_sizes[1];          // edges
    int n4 = in_sizes[0] / 4;      // grad float4 count
    int N  = in_sizes[0] / DIMV;   // nodes

    build_kernel<<<(E + 511) / 512, 512>>>(u_idx, v_idx, E);

    long long lanes = (long long)N * 8;
    int nblocks = (int)((lanes + 511) / 512) + 1;   // +1 block: overflow drain
    node_kernel<<<nblocks, 512>>>(x, N);

    copy_kernel<<<(n4 + 511) / 512, 512>>>(out, n4);
}

// round 16
// speedup vs baseline: 1.2548x; 1.0721x over previous
#include <cuda_runtime.h>

#define DIMV 64
#define GRAD_ELEMS 6400000   // N * DIM
#define GRAD_V4    1600000   // GRAD_ELEMS / 4
#define MAX_NODES  100000
#define CAP        64        // per-node slot capacity (Poisson(10) tail ~0)
#define OVER_CAP   1000000   // >= E: overflow can never drop

// Zero at module load. Per-call restore protocol (stream-ordered):
//   build(k):  zeroes g_grad (copy(k-1) already consumed it), bins edges
//   node(k):   accumulates g_grad, zeroes g_cnt, tail block drains g_over
//   copy(k):   reads g_grad -> out, resets g_energy/g_over_cnt
__device__ float g_grad[GRAD_ELEMS];
__device__ float g_energy;
__device__ int   g_cnt[MAX_NODES];
__device__ int   g_slots[MAX_NODES * CAP];
__device__ int2  g_over[OVER_CAP];
__device__ int   g_over_cnt;

__device__ __forceinline__ void red_add_v4(float* addr, float a, float b, float c, float d) {
    asm volatile("red.global.add.v4.f32 [%0], {%1, %2, %3, %4};"
                 :: "l"(addr), "f"(a), "f"(b), "f"(c), "f"(d)
                 : "memory");
}
__device__ __forceinline__ void red_add_f32(float* addr, float a) {
    asm volatile("red.global.add.f32 [%0], %1;"
                 :: "l"(addr), "f"(a) : "memory");
}

// ---------------------------------------------------------------------------
// Phase 1: bin edges by u (2 independent edges per thread -> 2 overlapped
// atomic/store chains, halves exposed latency) + zero g_grad.
// ---------------------------------------------------------------------------
__global__ __launch_bounds__(512)
void build_kernel(const int* __restrict__ u_idx,
                  const int* __restrict__ v_idx,
                  int E) {
    int t = blockIdx.x * blockDim.x + threadIdx.x;
    int total = gridDim.x * blockDim.x;

    // zero g_grad (grid-stride)
    float4* g = reinterpret_cast<float4*>(g_grad);
    float4 z = make_float4(0.f, 0.f, 0.f, 0.f);
    for (int j = t; j < GRAD_V4; j += total) g[j] = z;

    int half = (E + 1) >> 1;
    int e0 = t;
    int e1 = t + half;

    int u0 = 0, v0 = 0, u1 = 0, v1 = 0;
    bool do0 = (e0 < half) && (e0 < E);
    bool do1 = (e1 < E);
    if (do0) { u0 = u_idx[e0]; v0 = v_idx[e0]; }
    if (do1) { u1 = u_idx[e1]; v1 = v_idx[e1]; }

    int p0 = do0 ? atomicAdd(&g_cnt[u0], 1) : 0;
    int p1 = do1 ? atomicAdd(&g_cnt[u1], 1) : 0;

    if (do0) {
        if (p0 < CAP) g_slots[u0 * CAP + p0] = v0;
        else { int o = atomicAdd(&g_over_cnt, 1); g_over[o] = make_int2(u0, v0); }
    }
    if (do1) {
        if (p1 < CAP) g_slots[u1 * CAP + p1] = v1;
        else { int o = atomicAdd(&g_over_cnt, 1); g_over[o] = make_int2(u1, v1); }
    }
}

// ---------------------------------------------------------------------------
// Phase 2: node-centric, R5 loop shape (no prefetch). 8 lanes per node u;
// xu loaded once; u-grad in registers; v-grad scattered with red.v4 when
// active. In-loop shuffles use the 8-lane GROUP mask (cnt differs per group).
// Tail threads (u >= N) drain the overflow list.
// ---------------------------------------------------------------------------
__global__ __launch_bounds__(512)
void node_kernel(const float* __restrict__ x, int N) {
    int gid  = blockIdx.x * blockDim.x + threadIdx.x;
    int u    = gid >> 3;
    int sub  = gid & 7;
    int lane = threadIdx.x & 31;
    unsigned gmask = 0xFFu << (lane & ~7);

    float e_acc = 0.0f;

    if (u < N) {
        const float4* pu = reinterpret_cast<const float4*>(x + (size_t)u * DIMV) + 2 * sub;
        float4 a0 = pu[0], a1 = pu[1];
        float sgn = (sub == 0) ? -1.0f : 1.0f;

        int cnt = g_cnt[u];
        if (sub == 0) g_cnt[u] = 0;          // restore for next call
        if (cnt > CAP) cnt = CAP;
        const int* slots = g_slots + u * CAP;

        float4 ua0 = make_float4(0.f, 0.f, 0.f, 0.f);
        float4 ua1 = make_float4(0.f, 0.f, 0.f, 0.f);
        bool any_active = false;

        for (int i = 0; i < cnt; i++) {
            int v = slots[i];
            const float4* pv = reinterpret_cast<const float4*>(x + (size_t)v * DIMV) + 2 * sub;
            float4 b0 = pv[0], b1 = pv[1];

            float partial = sgn * (a0.x * b0.x) + a0.y * b0.y + a0.z * b0.z + a0.w * b0.w
                          + a1.x * b1.x + a1.y * b1.y + a1.z * b1.z + a1.w * b1.w;
            partial += __shfl_xor_sync(gmask, partial, 1);
            partial += __shfl_xor_sync(gmask, partial, 2);
            partial += __shfl_xor_sync(gmask, partial, 4);

            float inner = fminf(partial, -1.0f - 1e-7f);
            float s     = sqrtf(inner * inner - 1.0f);      // same fp32 form as reference
            float dist  = logf(-inner + s);                 // acosh(-inner)

            if (dist < 0.1f) {
                any_active = true;
                float delta = 0.1f - dist;
                if (sub == 0) e_acc += 5.0f * delta * delta;

                float factor = -__fdividef(10.0f * delta, s + 1e-9f);

                ua0.x += sgn * factor * b0.x;
                ua0.y += factor * b0.y;  ua0.z += factor * b0.z;  ua0.w += factor * b0.w;
                ua1.x += factor * b1.x;  ua1.y += factor * b1.y;
                ua1.z += factor * b1.z;  ua1.w += factor * b1.w;

                float* dv = g_grad + (size_t)v * DIMV + 8 * sub;
                red_add_v4(dv,     sgn * factor * a0.x, factor * a0.y, factor * a0.z, factor * a0.w);
                red_add_v4(dv + 4, factor * a1.x,       factor * a1.y, factor * a1.z, factor * a1.w);
            }
        }

        if (any_active) {
            float* du = g_grad + (size_t)u * DIMV + 8 * sub;
            red_add_v4(du,     ua0.x, ua0.y, ua0.z, ua0.w);
            red_add_v4(du + 4, ua1.x, ua1.y, ua1.z, ua1.w);
        }
    } else {
        // tail threads: drain overflow list (normally empty)
        int base = N * 8;
        int nthreads = gridDim.x * blockDim.x - base;
        int oc = g_over_cnt;
        for (int i = gid - base; i < oc; i += nthreads) {
            int w = g_over[i].x, p = g_over[i].y;
            const float* xw = x + (size_t)w * DIMV;
            const float* xp = x + (size_t)p * DIMV;
            float dot = -xw[0] * xp[0];
            for (int k = 1; k < DIMV; k++) dot += xw[k] * xp[k];
            float inner = fminf(dot, -1.0f - 1e-7f);
            float s     = sqrtf(inner * inner - 1.0f);
            float dist  = logf(-inner + s);
            if (dist < 0.1f) {
                float delta  = 0.1f - dist;
                float factor = -(10.0f * delta) / (s + 1e-9f);
                e_acc += 5.0f * delta * delta;
                float* gw = g_grad + (size_t)w * DIMV;
                float* gp = g_grad + (size_t)p * DIMV;
                atomicAdd(gw + 0, -factor * xp[0]);
                atomicAdd(gp + 0, -factor * xw[0]);
                for (int k = 1; k < DIMV; k++) {
                    atomicAdd(gw + k, factor * xp[k]);
                    atomicAdd(gp + k, factor * xw[k]);
                }
            }
        }
    }

    // block energy reduction (all lanes reconverged) -> one RED per block
    e_acc += __shfl_xor_sync(0xffffffffu, e_acc, 16);
    e_acc += __shfl_xor_sync(0xffffffffu, e_acc, 8);
    e_acc += __shfl_xor_sync(0xffffffffu, e_acc, 4);
    e_acc += __shfl_xor_sync(0xffffffffu, e_acc, 2);
    e_acc += __shfl_xor_sync(0xffffffffu, e_acc, 1);

    __shared__ float smem[16];
    int warp = threadIdx.x >> 5;
    if (lane == 0) smem[warp] = e_acc;
    __syncthreads();
    if (warp == 0) {
        float ss = (lane < 16) ? smem[lane] : 0.0f;
        ss += __shfl_xor_sync(0xffffffffu, ss, 8);
        ss += __shfl_xor_sync(0xffffffffu, ss, 4);
        ss += __shfl_xor_sync(0xffffffffu, ss, 2);
        ss += __shfl_xor_sync(0xffffffffu, ss, 1);
        if (lane == 0 && ss != 0.0f) red_add_f32(&g_energy, ss);
    }
}

// ---------------------------------------------------------------------------
// Phase 3: copy grad -> d_out (unaligned by 1 float), emit energy, reset
// scalars. No g_grad zeroing here — next call's build does it.
// ---------------------------------------------------------------------------
__global__ __launch_bounds__(512)
void copy_kernel(float* __restrict__ out, int n_grad4) {
    int j = blockIdx.x * blockDim.x + threadIdx.x;
    if (j < n_grad4) {
        const float4* g = reinterpret_cast<const float4*>(g_grad);
        float4 val = g[j];
        float* out_grad = out + 1;
        out_grad[4 * j + 0] = val.x;
        out_grad[4 * j + 1] = val.y;
        out_grad[4 * j + 2] = val.z;
        out_grad[4 * j + 3] = val.w;
    }
    if (j == 0) {
        out[0] = g_energy;
        g_energy = 0.0f;
        g_over_cnt = 0;
    }
}

extern "C" void kernel_launch(void* const* d_in, const int* in_sizes, int n_in,
                              void* d_out, int out_size) {
    const float* x     = (const float*)d_in[0];
    const int*   u_idx = (const int*)d_in[1];
    const int*   v_idx = (const int*)d_in[2];
    float*       out   = (float*)d_out;

    int E  = in_sizes[1];          // edges
    int n4 = in_sizes[0] / 4;      // grad float4 count
    int N  = in_sizes[0] / DIMV;   // nodes

    int half = (E + 1) >> 1;
    build_kernel<<<(half + 511) / 512, 512>>>(u_idx, v_idx, E);

    long long lanes = (long long)N * 8;
    int nblocks = (int)((lanes + 511) / 512) + 1;   // +1 block: overflow drain
    node_kernel<<<nblocks, 512>>>(x, N);

    copy_kernel<<<(n4 + 511) / 512, 512>>>(out, n4);
}